// round 4
// baseline (speedup 1.0000x reference)
#include <cuda_runtime.h>
#include <math.h>

#define N_NODES 50000
#define N_EDGES 800000
#define FEAT    128

#define NV4     (N_NODES / 4)                     // 12500 (exact)
#define SCAN_T  1024
#define SCAN_IT ((NV4 + SCAN_T - 1) / SCAN_T)     // 13

// Scratch (device globals; allocation in kernel_launch is forbidden).
__device__ float g_e[N_NODES];                          // e = x @ a
__device__ __align__(16) int   g_cnt[N_NODES];          // degree (zero on entry; re-zeroed by k_scan)
__device__ __align__(16) int   g_cursor[N_NODES];       // fill cursor (= rowptr copy)
__device__ __align__(16) int   g_rowptr[N_NODES + 4];   // CSR row pointers
__device__ int   g_cidx[N_EDGES];                       // CSR column indices
__device__ float g_vals[N_EDGES];                       // e[col] in CSR order

// K1: fused  e[i] = dot(x[i,:], a)  (warp per node)  +  degree histogram
// (thread per edge). Grid sized so threads = N_NODES*32 = 1.6M >= N_EDGES.
__global__ void k_score_count(const float* __restrict__ x,
                              const float* __restrict__ a,
                              const int* __restrict__ row) {
    __shared__ float sa[FEAT];
    int tid = threadIdx.x;
    if (tid < FEAT) sa[tid] = a[tid];
    __syncthreads();
    int gt = blockIdx.x * blockDim.x + tid;

    // edge counting (first N_EDGES threads)
    if (gt < N_EDGES) atomicAdd(&g_cnt[row[gt]], 1);

    // per-node score (warp per node)
    int gwarp = gt >> 5;
    int lane = tid & 31;
    if (gwarp >= N_NODES) return;
    float4 v = ((const float4*)x)[gwarp * 32 + lane];
    float4 w = ((const float4*)sa)[lane];
    float s = v.x * w.x + v.y * w.y + v.z * w.z + v.w * w.w;
    #pragma unroll
    for (int o = 16; o; o >>= 1) s += __shfl_xor_sync(0xffffffffu, s, o);
    if (lane == 0) g_e[gwarp] = s;
}

// K2: single-block exclusive scan of g_cnt -> g_rowptr (+ cursor copy),
// and re-zero g_cnt for the next graph replay. int4 vectorized, prefetch-1.
__global__ void __launch_bounds__(SCAN_T, 1) k_scan() {
    __shared__ int ws[32];
    int tid = threadIdx.x;
    int lane = tid & 31, w = tid >> 5;
    const int4 zero4 = make_int4(0, 0, 0, 0);

    int4 cur = (tid < NV4) ? ((const int4*)g_cnt)[tid] : zero4;
    int base = 0;

    #pragma unroll
    for (int it = 0; it < SCAN_IT; it++) {
        int nidx = (it + 1) * SCAN_T + tid;
        int4 nxt = (it + 1 < SCAN_IT && nidx < NV4) ? ((const int4*)g_cnt)[nidx] : zero4;

        int4 c = cur;
        int tsum = c.x + c.y + c.z + c.w;
        int s = tsum;
        #pragma unroll
        for (int o = 1; o < 32; o <<= 1) {
            int t = __shfl_up_sync(0xffffffffu, s, o);
            if (lane >= o) s += t;
        }
        if (lane == 31) ws[w] = s;
        __syncthreads();
        if (w == 0) {
            int t = ws[lane];
            #pragma unroll
            for (int o = 1; o < 32; o <<= 1) {
                int u = __shfl_up_sync(0xffffffffu, t, o);
                if (lane >= o) t += u;
            }
            ws[lane] = t;
        }
        __syncthreads();
        int excl = base + s - tsum + (w > 0 ? ws[w - 1] : 0);
        int total = ws[31];

        int idx = it * SCAN_T + tid;
        if (idx < NV4) {
            int4 out;
            out.x = excl;
            out.y = out.x + c.x;
            out.z = out.y + c.y;
            out.w = out.z + c.z;
            ((int4*)g_rowptr)[idx] = out;
            ((int4*)g_cursor)[idx] = out;
            ((int4*)g_cnt)[idx] = zero4;   // reset for next replay
        }
        base += total;
        cur = nxt;
        __syncthreads();   // protect ws before next iteration's writes
    }
    if (tid == 0) g_rowptr[N_NODES] = N_EDGES;
}

// K3: counting-sort fill: cidx + contiguous per-edge scores
__global__ void k_fill(const int* __restrict__ row, const int* __restrict__ col) {
    int k = blockIdx.x * blockDim.x + threadIdx.x;
    if (k >= N_EDGES) return;
    int r = row[k];
    int c = col[k];
    int pos = atomicAdd(&g_cursor[r], 1);
    g_cidx[pos] = c;
    g_vals[pos] = g_e[c];
}

// K4: warp per row — softmax on contiguous vals + weighted gather of x,
// register accumulator, single float4 store per lane. No atomics.
__global__ void k_row(const float* __restrict__ x, float* __restrict__ h) {
    int gw = (blockIdx.x * blockDim.x + threadIdx.x) >> 5;
    int lane = threadIdx.x & 31;
    if (gw >= N_NODES) return;
    int s0 = g_rowptr[gw], s1 = g_rowptr[gw + 1];

    // pass A: row max (contiguous lane-strided reads)
    float m = -INFINITY;
    for (int i = s0 + lane; i < s1; i += 32) m = fmaxf(m, g_vals[i]);
    #pragma unroll
    for (int o = 16; o; o >>= 1) m = fmaxf(m, __shfl_xor_sync(0xffffffffu, m, o));
    if (!isfinite(m)) m = 0.0f;

    // pass B: denom
    float ssum = 0.0f;
    for (int i = s0 + lane; i < s1; i += 32) ssum += __expf(g_vals[i] - m);
    #pragma unroll
    for (int o = 16; o; o >>= 1) ssum += __shfl_xor_sync(0xffffffffu, ssum, o);
    float inv = (s1 > s0) ? 1.0f / ssum : 0.0f;

    // pass C: weighted accumulate (serial over row edges; vals broadcast,
    // x row fully coalesced 512B per edge)
    float4 acc = make_float4(0.f, 0.f, 0.f, 0.f);
    for (int i = s0; i < s1; i++) {
        int c = g_cidx[i];
        float att = __expf(g_vals[i] - m) * inv;
        float4 v = ((const float4*)x)[c * 32 + lane];
        acc.x += att * v.x;
        acc.y += att * v.y;
        acc.z += att * v.z;
        acc.w += att * v.w;
    }
    ((float4*)h)[gw * 32 + lane] = acc;
}

extern "C" void kernel_launch(void* const* d_in, const int* in_sizes, int n_in,
                              void* d_out, int out_size) {
    const float* x   = (const float*)d_in[0];  // [N_NODES, FEAT]
    const float* a   = (const float*)d_in[1];  // [FEAT, 1]
    const int*   row = (const int*)d_in[2];    // [N_EDGES] int32
    const int*   col = (const int*)d_in[3];    // [N_EDGES] int32
    float* h = (float*)d_out;                  // [N_NODES, FEAT]

    int sc_blocks = (N_NODES * 32 + 255) / 256;      // warp/node + thread/edge
    k_score_count<<<sc_blocks, 256>>>(x, a, row);

    k_scan<<<1, SCAN_T>>>();

    int edge_blocks = (N_EDGES + 255) / 256;
    k_fill<<<edge_blocks, 256>>>(row, col);

    int row_blocks = (N_NODES * 32 + 255) / 256;     // warp per row
    k_row<<<row_blocks, 256>>>(x, h);
}

// round 5
// speedup vs baseline: 1.5106x; 1.5106x over previous
#include <cuda_runtime.h>
#include <math.h>

#define N_NODES 50000
#define N_EDGES 800000
#define FEAT    128
#define SCAN_BLOCKS 196   // ceil(50000/256)

// Scratch (device globals; no allocation allowed in kernel_launch).
__device__ float g_e[N_NODES];            // e = x @ a
__device__ int   g_cnt[N_NODES];          // degree
__device__ int   g_cursor[N_NODES];       // fill cursor
__device__ int   g_rowptr[N_NODES + 1];   // CSR row pointers
__device__ int   g_blocksum[SCAN_BLOCKS]; // scan partials
__device__ int   g_cidx[N_EDGES];         // CSR column indices
__device__ float g_vals[N_EDGES];         // e[col] in CSR order

// K1: e[i] = dot(x[i,:], a); also zero the degree counters.
__global__ void k_score(const float* __restrict__ x, const float* __restrict__ a) {
    __shared__ float sa[FEAT];
    int tid = threadIdx.x;
    if (tid < FEAT) sa[tid] = a[tid];
    __syncthreads();
    int gt = blockIdx.x * blockDim.x + tid;
    if (gt < N_NODES) g_cnt[gt] = 0;
    int gwarp = gt >> 5;
    int lane = tid & 31;
    if (gwarp >= N_NODES) return;
    float4 v = ((const float4*)x)[gwarp * 32 + lane];
    float4 w = ((const float4*)sa)[lane];
    float s = v.x * w.x + v.y * w.y + v.z * w.z + v.w * w.w;
    #pragma unroll
    for (int o = 16; o; o >>= 1) s += __shfl_xor_sync(0xffffffffu, s, o);
    if (lane == 0) g_e[gwarp] = s;
}

// K2: degree histogram
__global__ void k_count(const int* __restrict__ row) {
    int k = blockIdx.x * blockDim.x + threadIdx.x;
    if (k >= N_EDGES) return;
    atomicAdd(&g_cnt[row[k]], 1);
}

// K3a: per-block exclusive scan of g_cnt -> g_rowptr, block totals -> g_blocksum
__global__ void k_scan1() {
    int i = blockIdx.x * 256 + threadIdx.x;
    int v = (i < N_NODES) ? g_cnt[i] : 0;
    int lane = threadIdx.x & 31, w = threadIdx.x >> 5;
    int s = v;
    #pragma unroll
    for (int o = 1; o < 32; o <<= 1) {
        int t = __shfl_up_sync(0xffffffffu, s, o);
        if (lane >= o) s += t;
    }
    __shared__ int ws[8];
    if (lane == 31) ws[w] = s;
    __syncthreads();
    if (w == 0) {
        int t = (lane < 8) ? ws[lane] : 0;
        #pragma unroll
        for (int o = 1; o < 8; o <<= 1) {
            int u = __shfl_up_sync(0xffffffffu, t, o);
            if (lane >= o) t += u;
        }
        if (lane < 8) ws[lane] = t;
    }
    __syncthreads();
    int excl = s - v + (w > 0 ? ws[w - 1] : 0);
    if (i < N_NODES) g_rowptr[i] = excl;
    if (threadIdx.x == 0) g_blocksum[blockIdx.x] = ws[7];
}

// K3b: exclusive scan of block sums (single block)
__global__ void k_scan2() {
    int i = threadIdx.x;
    int v = (i < SCAN_BLOCKS) ? g_blocksum[i] : 0;
    int lane = i & 31, w = i >> 5;
    int s = v;
    #pragma unroll
    for (int o = 1; o < 32; o <<= 1) {
        int t = __shfl_up_sync(0xffffffffu, s, o);
        if (lane >= o) s += t;
    }
    __shared__ int ws[8];
    if (lane == 31) ws[w] = s;
    __syncthreads();
    if (w == 0) {
        int t = (lane < 8) ? ws[lane] : 0;
        #pragma unroll
        for (int o = 1; o < 8; o <<= 1) {
            int u = __shfl_up_sync(0xffffffffu, t, o);
            if (lane >= o) t += u;
        }
        if (lane < 8) ws[lane] = t;
    }
    __syncthreads();
    int excl = s - v + (w > 0 ? ws[w - 1] : 0);
    if (i < SCAN_BLOCKS) g_blocksum[i] = excl;
}

// K3c: add block offsets, zero cursors, cap rowptr
__global__ void k_scan3() {
    int i = blockIdx.x * 256 + threadIdx.x;
    if (i < N_NODES) {
        g_rowptr[i] += g_blocksum[i >> 8];
        g_cursor[i] = 0;
    }
    if (i == 0) g_rowptr[N_NODES] = N_EDGES;
}

// K4: counting-sort fill of column indices + contiguous per-edge scores
__global__ void k_fill(const int* __restrict__ row, const int* __restrict__ col) {
    int k = blockIdx.x * blockDim.x + threadIdx.x;
    if (k >= N_EDGES) return;
    int r = row[k];
    int c = col[k];
    int pos = g_rowptr[r] + atomicAdd(&g_cursor[r], 1);
    g_cidx[pos] = c;
    g_vals[pos] = g_e[c];
}

// K5: warp per row — softmax on contiguous vals + weighted x gather.
// Pass C manually unrolled x4: four independent float4 loads in flight
// per warp to hide L2 latency. Register accumulator, one store. No atomics.
__global__ void k_row(const float* __restrict__ x, float* __restrict__ h) {
    int gw = (blockIdx.x * blockDim.x + threadIdx.x) >> 5;
    int lane = threadIdx.x & 31;
    if (gw >= N_NODES) return;
    int s0 = g_rowptr[gw], s1 = g_rowptr[gw + 1];

    // pass A: row max (contiguous)
    float m = -INFINITY;
    for (int i = s0 + lane; i < s1; i += 32) m = fmaxf(m, g_vals[i]);
    #pragma unroll
    for (int o = 16; o; o >>= 1) m = fmaxf(m, __shfl_xor_sync(0xffffffffu, m, o));
    if (!isfinite(m)) m = 0.0f;

    // pass B: denom (contiguous)
    float ssum = 0.0f;
    for (int i = s0 + lane; i < s1; i += 32) ssum += __expf(g_vals[i] - m);
    #pragma unroll
    for (int o = 16; o; o >>= 1) ssum += __shfl_xor_sync(0xffffffffu, ssum, o);
    float inv = (s1 > s0) ? 1.0f / ssum : 0.0f;

    // pass C: weighted accumulate, 4 edges per iteration (MLP=4)
    const float4* x4 = (const float4*)x;
    float4 acc = make_float4(0.f, 0.f, 0.f, 0.f);
    int i = s0;
    for (; i + 4 <= s1; i += 4) {
        int c0 = g_cidx[i + 0];
        int c1 = g_cidx[i + 1];
        int c2 = g_cidx[i + 2];
        int c3 = g_cidx[i + 3];
        float4 v0 = x4[c0 * 32 + lane];
        float4 v1 = x4[c1 * 32 + lane];
        float4 v2 = x4[c2 * 32 + lane];
        float4 v3 = x4[c3 * 32 + lane];
        float a0 = __expf(g_vals[i + 0] - m) * inv;
        float a1 = __expf(g_vals[i + 1] - m) * inv;
        float a2 = __expf(g_vals[i + 2] - m) * inv;
        float a3 = __expf(g_vals[i + 3] - m) * inv;
        acc.x += a0 * v0.x + a1 * v1.x + a2 * v2.x + a3 * v3.x;
        acc.y += a0 * v0.y + a1 * v1.y + a2 * v2.y + a3 * v3.y;
        acc.z += a0 * v0.z + a1 * v1.z + a2 * v2.z + a3 * v3.z;
        acc.w += a0 * v0.w + a1 * v1.w + a2 * v2.w + a3 * v3.w;
    }
    for (; i < s1; i++) {
        int c = g_cidx[i];
        float att = __expf(g_vals[i] - m) * inv;
        float4 v = x4[c * 32 + lane];
        acc.x += att * v.x;
        acc.y += att * v.y;
        acc.z += att * v.z;
        acc.w += att * v.w;
    }
    ((float4*)h)[gw * 32 + lane] = acc;
}

extern "C" void kernel_launch(void* const* d_in, const int* in_sizes, int n_in,
                              void* d_out, int out_size) {
    const float* x   = (const float*)d_in[0];  // [N_NODES, FEAT]
    const float* a   = (const float*)d_in[1];  // [FEAT, 1]
    const int*   row = (const int*)d_in[2];    // [N_EDGES] int32
    const int*   col = (const int*)d_in[3];    // [N_EDGES] int32
    float* h = (float*)d_out;                  // [N_NODES, FEAT]

    int score_blocks = (N_NODES * 32 + 255) / 256;   // warp per node
    k_score<<<score_blocks, 256>>>(x, a);

    int edge_blocks = (N_EDGES + 255) / 256;
    k_count<<<edge_blocks, 256>>>(row);

    k_scan1<<<SCAN_BLOCKS, 256>>>();
    k_scan2<<<1, 256>>>();
    k_scan3<<<SCAN_BLOCKS, 256>>>();

    k_fill<<<edge_blocks, 256>>>(row, col);

    int row_blocks = (N_NODES * 32 + 255) / 256;     // warp per row
    k_row<<<row_blocks, 256>>>(x, h);
}

// round 6
// speedup vs baseline: 1.6512x; 1.0930x over previous
#include <cuda_runtime.h>
#include <cuda_fp16.h>
#include <math.h>

#define N_NODES 50000
#define N_EDGES 800000
#define FEAT    128
#define SCAN_BLOCKS 196   // ceil(50000/256)

// Scratch (device globals; no allocation allowed in kernel_launch).
__device__ float g_e[N_NODES];                        // e = x @ a
__device__ int   g_cnt[N_NODES];                      // degree (re-zeroed by scanA)
__device__ int   g_cursor[N_NODES];                   // fill cursor
__device__ int   g_rowptr[N_NODES + 1];               // CSR row pointers
__device__ int   g_blocksum[SCAN_BLOCKS];             // scan partials
__device__ int   g_cidx[N_EDGES];                     // CSR column indices
__device__ float g_vals[N_EDGES];                     // e[col] in CSR order
__device__ __align__(16) __half g_xh[N_NODES * FEAT]; // fp16 copy of x (gathered in k_row)

// K1: fused — e[i] = dot(x[i,:], a) (warp per node), fp16 copy of x,
// and degree histogram (thread per edge; grid has 1.6M threads >= N_EDGES).
// g_cnt is zero on entry (module-load zero-init, then re-zeroed by scanA).
__global__ void k_score(const float* __restrict__ x, const float* __restrict__ a,
                        const int* __restrict__ row) {
    __shared__ float sa[FEAT];
    int tid = threadIdx.x;
    if (tid < FEAT) sa[tid] = a[tid];
    __syncthreads();
    int gt = blockIdx.x * blockDim.x + tid;

    if (gt < N_EDGES) atomicAdd(&g_cnt[row[gt]], 1);

    int gwarp = gt >> 5;
    int lane = tid & 31;
    if (gwarp >= N_NODES) return;
    float4 v = ((const float4*)x)[gwarp * 32 + lane];

    // fp16 copy for the gather phase
    __half2 p0 = __floats2half2_rn(v.x, v.y);
    __half2 p1 = __floats2half2_rn(v.z, v.w);
    uint2 packed;
    packed.x = *(unsigned int*)&p0;
    packed.y = *(unsigned int*)&p1;
    ((uint2*)g_xh)[gwarp * 32 + lane] = packed;

    float4 w = ((const float4*)sa)[lane];
    float s = v.x * w.x + v.y * w.y + v.z * w.z + v.w * w.w;
    #pragma unroll
    for (int o = 16; o; o >>= 1) s += __shfl_xor_sync(0xffffffffu, s, o);
    if (lane == 0) g_e[gwarp] = s;
}

// K2a: per-block exclusive scan of g_cnt -> g_rowptr (local), totals -> g_blocksum.
// Also re-zeroes g_cnt for the next graph replay.
__global__ void k_scanA() {
    int i = blockIdx.x * 256 + threadIdx.x;
    int v = 0;
    if (i < N_NODES) { v = g_cnt[i]; g_cnt[i] = 0; }
    int lane = threadIdx.x & 31, w = threadIdx.x >> 5;
    int s = v;
    #pragma unroll
    for (int o = 1; o < 32; o <<= 1) {
        int t = __shfl_up_sync(0xffffffffu, s, o);
        if (lane >= o) s += t;
    }
    __shared__ int ws[8];
    if (lane == 31) ws[w] = s;
    __syncthreads();
    if (w == 0) {
        int t = (lane < 8) ? ws[lane] : 0;
        #pragma unroll
        for (int o = 1; o < 8; o <<= 1) {
            int u = __shfl_up_sync(0xffffffffu, t, o);
            if (lane >= o) t += u;
        }
        if (lane < 8) ws[lane] = t;
    }
    __syncthreads();
    int excl = s - v + (w > 0 ? ws[w - 1] : 0);
    if (i < N_NODES) g_rowptr[i] = excl;
    if (threadIdx.x == 0) g_blocksum[blockIdx.x] = ws[7];
}

// K2b: each block computes its prefix over g_blocksum by block-reduce,
// adds it to its rowptr slice, and seeds the cursor. Replaces grid=1 scan.
__global__ void k_scanB() {
    int tid = threadIdx.x;
    int v = (tid < SCAN_BLOCKS && tid < blockIdx.x) ? g_blocksum[tid] : 0;
    int lane = tid & 31, w = tid >> 5;
    #pragma unroll
    for (int o = 16; o; o >>= 1) v += __shfl_xor_sync(0xffffffffu, v, o);
    __shared__ int ws[8];
    if (lane == 0) ws[w] = v;
    __syncthreads();
    if (tid == 0) {
        int t = 0;
        #pragma unroll
        for (int j = 0; j < 8; j++) t += ws[j];
        ws[0] = t;
    }
    __syncthreads();
    int prefix = ws[0];

    int i = blockIdx.x * 256 + tid;
    if (i < N_NODES) {
        int rp = g_rowptr[i] + prefix;
        g_rowptr[i] = rp;
        g_cursor[i] = rp;
    }
    if (i == 0) g_rowptr[N_NODES] = N_EDGES;
}

// K3: counting-sort fill of column indices + contiguous per-edge scores
__global__ void k_fill(const int* __restrict__ row, const int* __restrict__ col) {
    int k = blockIdx.x * blockDim.x + threadIdx.x;
    if (k >= N_EDGES) return;
    int r = row[k];
    int c = col[k];
    int pos = atomicAdd(&g_cursor[r], 1);
    g_cidx[pos] = c;
    g_vals[pos] = g_e[c];
}

// K4: warp per row — max pass on contiguous vals, then a single fused pass
// that accumulates unnormalized exp-weighted fp16 features + the weight sum,
// scaling once at the end. fp16 gather = 256B/edge (half the fp32 traffic).
__global__ void k_row(float* __restrict__ h) {
    int gw = (blockIdx.x * blockDim.x + threadIdx.x) >> 5;
    int lane = threadIdx.x & 31;
    if (gw >= N_NODES) return;
    int s0 = g_rowptr[gw], s1 = g_rowptr[gw + 1];

    // pass A: row max (contiguous)
    float m = -INFINITY;
    for (int i = s0 + lane; i < s1; i += 32) m = fmaxf(m, g_vals[i]);
    #pragma unroll
    for (int o = 16; o; o >>= 1) m = fmaxf(m, __shfl_xor_sync(0xffffffffu, m, o));
    if (!isfinite(m)) m = 0.0f;

    // pass B+C fused: unnormalized accumulate + weight sum (warp-uniform)
    const uint2* xh = (const uint2*)g_xh;
    float4 acc = make_float4(0.f, 0.f, 0.f, 0.f);
    float wsum = 0.0f;
    for (int i = s0; i < s1; i++) {
        int c = g_cidx[i];
        float wgt = __expf(g_vals[i] - m);
        wsum += wgt;
        uint2 p = xh[c * 32 + lane];
        __half2 h0 = *(__half2*)&p.x;
        __half2 h1 = *(__half2*)&p.y;
        float2 f0 = __half22float2(h0);
        float2 f1 = __half22float2(h1);
        acc.x += wgt * f0.x;
        acc.y += wgt * f0.y;
        acc.z += wgt * f1.x;
        acc.w += wgt * f1.y;
    }
    float inv = (s1 > s0) ? 1.0f / wsum : 0.0f;
    acc.x *= inv; acc.y *= inv; acc.z *= inv; acc.w *= inv;
    ((float4*)h)[gw * 32 + lane] = acc;
}

extern "C" void kernel_launch(void* const* d_in, const int* in_sizes, int n_in,
                              void* d_out, int out_size) {
    const float* x   = (const float*)d_in[0];  // [N_NODES, FEAT]
    const float* a   = (const float*)d_in[1];  // [FEAT, 1]
    const int*   row = (const int*)d_in[2];    // [N_EDGES] int32
    const int*   col = (const int*)d_in[3];    // [N_EDGES] int32
    float* h = (float*)d_out;                  // [N_NODES, FEAT]

    int score_blocks = (N_NODES * 32 + 255) / 256;   // warp/node + thread/edge
    k_score<<<score_blocks, 256>>>(x, a, row);

    k_scanA<<<SCAN_BLOCKS, 256>>>();
    k_scanB<<<SCAN_BLOCKS, 256>>>();

    int edge_blocks = (N_EDGES + 255) / 256;
    k_fill<<<edge_blocks, 256>>>(row, col);

    int row_blocks = (N_NODES * 32 + 255) / 256;     // warp per row
    k_row<<<row_blocks, 256>>>(h);
}